// round 15
// baseline (speedup 1.0000x reference)
#include <cuda_runtime.h>
#include <cstdint>

#define N_NODES 20000
#define N_EDGES 640000
#define FEAT 8
#define OUT 64
#define PERIODS 12
#define XDIM 96
#define CAP 128
#define MB2 144
#define THR 576
#define XS 84   // X smem row stride (floats)

typedef unsigned long long u64;
typedef unsigned int u32;

__device__ __align__(16) int   g_cursor[N_NODES];
__device__ __align__(16) int   g_srcs[N_NODES * CAP];
__device__ __align__(16) float g_Ax[N_NODES * XDIM];   // t-major rows
__device__ __align__(16) float g_WP[3 * FEAT * OUT];
__device__ __align__(16) float g_BP[3 * OUT];
__device__ float g_probs[PERIODS];

__device__ __forceinline__ float tanha(float v) {
    float r; asm("tanh.approx.f32 %0, %1;" : "=f"(r) : "f"(v)); return r;
}
__device__ __forceinline__ float sigf(float v) { return fmaf(0.5f, tanha(0.5f * v), 0.5f); }
__device__ __forceinline__ float rna_tf32(float v) {
    float r; asm("cvt.rna.tf32.f32 %0, %1;" : "=f"(r) : "f"(v)); return r;
}
__device__ __forceinline__ void mma8(float* d, u32 a0, u32 a1, u32 a2, u32 a3,
                                     u32 b0, u32 b1) {
    asm volatile("mma.sync.aligned.m16n8k8.row.col.f32.tf32.tf32.f32 "
        "{%0,%1,%2,%3}, {%4,%5,%6,%7}, {%8,%9}, {%0,%1,%2,%3};"
        : "+f"(d[0]), "+f"(d[1]), "+f"(d[2]), "+f"(d[3])
        : "r"(a0), "r"(a1), "r"(a2), "r"(a3), "r"(b0), "r"(b1));
}
__device__ __forceinline__ void barpair(int tile) {
    asm volatile("bar.sync %0, %1;" :: "r"(tile + 1), "r"(64) : "memory");
}

// ---- K1: zero cursors + fold weights ----
__global__ void k_init(const float* Wz, const float* bz, const float* Lz, const float* Lzb,
                       const float* Wr, const float* br, const float* Lr, const float* Lrb,
                       const float* Wh, const float* bh, const float* Lh, const float* Lhb,
                       const float* att) {
    int i = blockIdx.x * blockDim.x + threadIdx.x;
    if (i < N_NODES) g_cursor[i] = 0;
    if (blockIdx.x == 0) {
        const float* W[3] = {Wz, Wr, Wh};
        const float* L[3] = {Lz, Lr, Lh};
        const float* B[3] = {bz, br, bh};
        const float* LB[3] = {Lzb, Lrb, Lhb};
        int tid = threadIdx.x;
        for (int idx = tid; idx < 3 * FEAT * OUT; idx += blockDim.x) {
            int g = idx / (FEAT * OUT), r = idx - g * (FEAT * OUT), f = r / OUT, o = r % OUT;
            float s = 0.0f;
            for (int k = 0; k < OUT; k++) s = fmaf(W[g][f * OUT + k], L[g][k * OUT + o], s);
            g_WP[idx] = s;
        }
        for (int idx = tid; idx < 3 * OUT; idx += blockDim.x) {
            int g = idx / OUT, o = idx % OUT;
            float s = LB[g][o];
            for (int k = 0; k < OUT; k++) s = fmaf(B[g][k], L[g][k * OUT + o], s);
            g_BP[idx] = s;
        }
        if (tid == 0) {
            float m = att[0];
            for (int t = 1; t < PERIODS; t++) m = fmaxf(m, att[t]);
            float e[PERIODS], sum = 0.0f;
            for (int t = 0; t < PERIODS; t++) { e[t] = __expf(att[t] - m); sum += e[t]; }
            float inv = __fdividef(1.0f, sum);
            for (int t = 0; t < PERIODS; t++) g_probs[t] = e[t] * inv;
        }
    }
}
__global__ void k_fill(const int* __restrict__ ei) {
    int e = blockIdx.x * blockDim.x + threadIdx.x;
    if (e >= N_EDGES) return;
    int s = ei[e], d = ei[N_EDGES + e];
    int pos = atomicAdd(&g_cursor[d], 1);
    if (pos < CAP) g_srcs[d * CAP + pos] = s;
}

// ---- gather: TWO warps per node (halved latency exposure), transposed write ----
__global__ void __launch_bounds__(256) k_gather(const float* __restrict__ x) {
    __shared__ float part[4][96];
    int wid = threadIdx.x >> 5, lane = threadIdx.x & 31;
    int pairid = wid >> 1, halfid = wid & 1;
    int node = blockIdx.x * 4 + pairid;

    float a0 = 0.f, a1 = 0.f, a2 = 0.f;
    int deg = 0;
    if (node < N_NODES) {
        deg = g_cursor[node];
        int ndeg = min(deg, CAP);
        int mid = (ndeg + 1) >> 1;
        int beg = halfid ? mid : 0;
        int end = halfid ? ndeg : mid;
        const int* bucket = g_srcs + node * CAP;
        for (int j0 = beg; j0 < end; j0 += 32) {
            int idx = j0 + lane;
            int sj = (idx < end) ? bucket[idx] : 0;
            float dv = (idx < end) ? rsqrtf((float)g_cursor[sj] + 1.0f) : 0.0f;
            int lim = min(32, end - j0);
#pragma unroll 4
            for (int jj = 0; jj < lim; jj++) {
                int s = __shfl_sync(0xffffffffu, sj, jj);
                float d = __shfl_sync(0xffffffffu, dv, jj);
                const float* row = x + s * XDIM;
                a0 = fmaf(d, row[lane], a0);
                a1 = fmaf(d, row[lane + 32], a1);
                a2 = fmaf(d, row[lane + 64], a2);
            }
        }
        if (halfid) {
            part[pairid][lane] = a0;
            part[pairid][lane + 32] = a1;
            part[pairid][lane + 64] = a2;
        }
    }
    __syncthreads();
    if (halfid == 0 && node < N_NODES) {
        a0 += part[pairid][lane];
        a1 += part[pairid][lane + 32];
        a2 += part[pairid][lane + 64];
        float dd = rsqrtf((float)deg + 1.0f);
        const float* self = x + node * XDIM;
        float* dst = g_Ax + node * XDIM;
        int c0 = lane, c1 = lane + 32, c2 = lane + 64;
        dst[(c0 % PERIODS) * 8 + c0 / PERIODS] = dd * fmaf(dd, self[c0], a0);
        dst[(c1 % PERIODS) * 8 + c1 / PERIODS] = dd * fmaf(dd, self[c1], a1);
        dst[(c2 % PERIODS) * 8 + c2 / PERIODS] = dd * fmaf(dd, self[c2], a2);
    }
}

// ---- fused mma.sync kernel: 2 warps per 16-row tile (n split 32/32) ----
struct FS2 {
    float  X[MB2][XS];
    float4 WZR[9][8][32];
    float2 WH[9][8][32];
    float  BP[3][OUT];
    float  probs[PERIODS];
};

__device__ __forceinline__ float welem(const float* Lg, int g, int n, int k) {
    return (k < 64) ? Lg[(64 + k) * 64 + n] : g_WP[g * 512 + (k - 64) * 64 + n];
}

__global__ void __launch_bounds__(THR, 1)
k_fused(const float* __restrict__ Lz, const float* __restrict__ Lr,
        const float* __restrict__ Lh, const float* __restrict__ hw,
        const float* __restrict__ hb, float* __restrict__ out) {
    extern __shared__ char smraw[];
    FS2* sm = (FS2*)smraw;
    const int tid = threadIdx.x;
    const int w = tid >> 5, lane = tid & 31;
    const int tile = w >> 1, side = w & 1;
    const int grp = lane >> 2, tig = lane & 3;
    const int wrow = tile * 16;
    const int ntb = side * 4;
    const int nb = blockIdx.x * MB2;

    for (int i = tid; i < 9 * 8 * 32; i += THR) {
        int kb = i / 256, rem = i & 255, nt = rem >> 5, ln = rem & 31;
        int g2 = ln >> 2, t2 = ln & 3;
        int kA = kb * 8 + 2 * t2, kB = kA + 1, nrow = nt * 8 + g2;
        float4 zr;
        zr.x = rna_tf32(welem(Lz, 0, nrow, kA));
        zr.y = rna_tf32(welem(Lz, 0, nrow, kB));
        zr.z = rna_tf32(welem(Lr, 1, nrow, kA));
        zr.w = rna_tf32(welem(Lr, 1, nrow, kB));
        sm->WZR[kb][nt][ln] = zr;
        sm->WH[kb][nt][ln] = make_float2(rna_tf32(welem(Lh, 2, nrow, kA)),
                                         rna_tf32(welem(Lh, 2, nrow, kB)));
    }
    for (int i = tid; i < 3 * OUT; i += THR) (&sm->BP[0][0])[i] = g_BP[i];
    if (tid < PERIODS) sm->probs[tid] = g_probs[tid];
    for (int i = tid; i < MB2 * OUT; i += THR) sm->X[i >> 6][i & 63] = 0.0f;
    __syncthreads();

    const int row0 = wrow + grp, row1 = row0 + 8;
    const int arow = wrow + (lane >> 1);
    const int anode = nb + arow;
    const bool aok = (anode < N_NODES);

    float hacc[16];
#pragma unroll
    for (int i = 0; i < 16; i++) hacc[i] = 0.0f;

    for (int t = 0; t < PERIODS; t++) {
        float p = sm->probs[t];

        if (side == 0) {
            int acol = (lane & 1) * 4;
            float4 av = make_float4(0.f, 0.f, 0.f, 0.f);
            if (aok) av = *(const float4*)(g_Ax + anode * XDIM + t * 8 + acol);
            *(float4*)&sm->X[arow][64 + acol] =
                make_float4(rna_tf32(av.x), rna_tf32(av.y), rna_tf32(av.z), rna_tf32(av.w));
        }
        barpair(tile);

        // cache Ax A-frags (kb=8) once — reused by both GEMM phases
        float2 ax_a = *(float2*)&sm->X[row0][64 + 2 * tig];
        float2 ax_b = *(float2*)&sm->X[row1][64 + 2 * tig];
        u32 x8a0 = __float_as_uint(ax_a.x), x8a2 = __float_as_uint(ax_a.y);
        u32 x8a1 = __float_as_uint(ax_b.x), x8a3 = __float_as_uint(ax_b.y);

        // ---- z and r GEMMs ----
        float az[16], ar[16];
#pragma unroll
        for (int i = 0; i < 16; i++) { az[i] = 0.0f; ar[i] = 0.0f; }
#pragma unroll
        for (int kb = 0; kb < 8; kb++) {
            float2 va = *(float2*)&sm->X[row0][kb * 8 + 2 * tig];
            float2 vb = *(float2*)&sm->X[row1][kb * 8 + 2 * tig];
            u32 a0 = __float_as_uint(va.x), a2 = __float_as_uint(va.y);
            u32 a1 = __float_as_uint(vb.x), a3 = __float_as_uint(vb.y);
#pragma unroll
            for (int nt = 0; nt < 4; nt++) {
                float4 b = sm->WZR[kb][ntb + nt][lane];
                mma8(az + nt * 4, a0, a1, a2, a3, __float_as_uint(b.x), __float_as_uint(b.y));
                mma8(ar + nt * 4, a0, a1, a2, a3, __float_as_uint(b.z), __float_as_uint(b.w));
            }
        }
#pragma unroll
        for (int nt = 0; nt < 4; nt++) {
            float4 b = sm->WZR[8][ntb + nt][lane];
            mma8(az + nt * 4, x8a0, x8a1, x8a2, x8a3, __float_as_uint(b.x), __float_as_uint(b.y));
            mma8(ar + nt * 4, x8a0, x8a1, x8a2, x8a3, __float_as_uint(b.z), __float_as_uint(b.w));
        }

        // ---- epilogue 1 ----
#pragma unroll
        for (int nt = 0; nt < 4; nt++) {
            int c0 = (ntb + nt) * 8 + tig * 2;
            float2 bz = *(float2*)&sm->BP[0][c0];
            float2 br = *(float2*)&sm->BP[1][c0];
            float2 h01 = *(float2*)&sm->X[row0][c0];
            float2 h23 = *(float2*)&sm->X[row1][c0];
            float z0 = sigf(az[nt*4+0] + bz.x), z1 = sigf(az[nt*4+1] + bz.y);
            float z2 = sigf(az[nt*4+2] + bz.x), z3 = sigf(az[nt*4+3] + bz.y);
            float r0 = sigf(ar[nt*4+0] + br.x), r1 = sigf(ar[nt*4+1] + br.y);
            float r2 = sigf(ar[nt*4+2] + br.x), r3 = sigf(ar[nt*4+3] + br.y);
            *(float2*)&sm->X[row0][c0] = make_float2(rna_tf32(r0 * h01.x), rna_tf32(r1 * h01.y));
            *(float2*)&sm->X[row1][c0] = make_float2(rna_tf32(r2 * h23.x), rna_tf32(r3 * h23.y));
            az[nt*4+0] = z0; az[nt*4+1] = z1; az[nt*4+2] = z2; az[nt*4+3] = z3;
            ar[nt*4+0] = h01.x; ar[nt*4+1] = h01.y; ar[nt*4+2] = h23.x; ar[nt*4+3] = h23.y;
        }
        barpair(tile);

        // ---- h GEMM ----
        float ah[16];
#pragma unroll
        for (int i = 0; i < 16; i++) ah[i] = 0.0f;
#pragma unroll
        for (int kb = 0; kb < 8; kb++) {
            float2 va = *(float2*)&sm->X[row0][kb * 8 + 2 * tig];
            float2 vb = *(float2*)&sm->X[row1][kb * 8 + 2 * tig];
            u32 a0 = __float_as_uint(va.x), a2 = __float_as_uint(va.y);
            u32 a1 = __float_as_uint(vb.x), a3 = __float_as_uint(vb.y);
#pragma unroll
            for (int nt = 0; nt < 4; nt++) {
                float2 b = sm->WH[kb][ntb + nt][lane];
                mma8(ah + nt * 4, a0, a1, a2, a3, __float_as_uint(b.x), __float_as_uint(b.y));
            }
        }
#pragma unroll
        for (int nt = 0; nt < 4; nt++) {
            float2 b = sm->WH[8][ntb + nt][lane];
            mma8(ah + nt * 4, x8a0, x8a1, x8a2, x8a3, __float_as_uint(b.x), __float_as_uint(b.y));
        }

        // ---- epilogue 2 ----
#pragma unroll
        for (int nt = 0; nt < 4; nt++) {
            int c0 = (ntb + nt) * 8 + tig * 2;
            float2 bh = *(float2*)&sm->BP[2][c0];
            float hn[4];
#pragma unroll
            for (int q = 0; q < 4; q++) {
                float bb = (q & 1) ? bh.y : bh.x;
                float ht = tanha(ah[nt*4+q] + bb);
                float z = az[nt*4+q], hd = ar[nt*4+q];
                float v = z * hd + (1.0f - z) * ht;
                hacc[nt*4+q] = fmaf(p, v, hacc[nt*4+q]);
                hn[q] = rna_tf32(v);
            }
            *(float2*)&sm->X[row0][c0] = make_float2(hn[0], hn[1]);
            *(float2*)&sm->X[row1][c0] = make_float2(hn[2], hn[3]);
        }
        barpair(tile);
    }

    // ---- head ----
#pragma unroll
    for (int nt = 0; nt < 4; nt++) {
        int c0 = (ntb + nt) * 8 + tig * 2;
        *(float2*)&sm->X[row0][c0] =
            make_float2(fmaxf(hacc[nt*4+0], 0.f), fmaxf(hacc[nt*4+1], 0.f));
        *(float2*)&sm->X[row1][c0] =
            make_float2(fmaxf(hacc[nt*4+2], 0.f), fmaxf(hacc[nt*4+3], 0.f));
    }
    __syncthreads();

    float* sW = (float*)&sm->WZR[0][0][0];
    float* sB = &sm->BP[0][0];
    for (int i = tid; i < OUT * PERIODS; i += THR) sW[i] = hw[i];
    if (tid < PERIODS) sB[tid] = hb[tid];
    __syncthreads();

    for (int i = tid; i < MB2 * PERIODS; i += THR) {
        int nn = i / PERIODS, pp = i - nn * PERIODS;
        int node = nb + nn;
        if (node >= N_NODES) continue;
        float acc = sB[pp];
#pragma unroll 16
        for (int o = 0; o < OUT; o++)
            acc = fmaf(sm->X[nn][o], sW[o * PERIODS + pp], acc);
        out[node * PERIODS + pp] = acc;
    }
}

extern "C" void kernel_launch(void* const* d_in, const int* in_sizes, int n_in,
                              void* d_out, int out_size) {
    const float* x   = (const float*)d_in[0];
    const int*   ei  = (const int*)d_in[1];
    const float* Wz  = (const float*)d_in[2];
    const float* bz  = (const float*)d_in[3];
    const float* LzW = (const float*)d_in[4];
    const float* Lzb = (const float*)d_in[5];
    const float* Wr  = (const float*)d_in[6];
    const float* br  = (const float*)d_in[7];
    const float* LrW = (const float*)d_in[8];
    const float* Lrb = (const float*)d_in[9];
    const float* Wh  = (const float*)d_in[10];
    const float* bh  = (const float*)d_in[11];
    const float* LhW = (const float*)d_in[12];
    const float* Lhb = (const float*)d_in[13];
    const float* att = (const float*)d_in[14];
    const float* hW  = (const float*)d_in[15];
    const float* hb  = (const float*)d_in[16];
    float* out = (float*)d_out;

    cudaFuncSetAttribute(k_fused, cudaFuncAttributeMaxDynamicSharedMemorySize, (int)sizeof(FS2));

    k_init<<<(N_NODES + 255) / 256, 256>>>(Wz, bz, LzW, Lzb, Wr, br, LrW, Lrb,
                                           Wh, bh, LhW, Lhb, att);
    k_fill<<<(N_EDGES + 255) / 256, 256>>>(ei);
    k_gather<<<(N_NODES + 3) / 4, 256>>>(x);
    k_fused<<<(N_NODES + MB2 - 1) / MB2, THR, sizeof(FS2)>>>(LzW, LrW, LhW, hW, hb, out);
}

// round 16
// speedup vs baseline: 1.0520x; 1.0520x over previous
#include <cuda_runtime.h>
#include <cstdint>

#define N_NODES 20000
#define N_EDGES 640000
#define FEAT 8
#define OUT 64
#define PERIODS 12
#define XDIM 96
#define CAP 128
#define MB2 144
#define THR 576
#define XS 84   // X smem row stride (floats)

typedef unsigned long long u64;
typedef unsigned int u32;

__device__ __align__(16) int   g_cursor[N_NODES];
__device__ __align__(16) int   g_srcs[N_NODES * CAP];
__device__ __align__(16) float g_Ax[N_NODES * XDIM];   // t-major rows
__device__ __align__(16) float g_WP[3 * FEAT * OUT];
__device__ __align__(16) float g_BP[3 * OUT];
__device__ float g_probs[PERIODS];

__device__ __forceinline__ float tanha(float v) {
    float r; asm("tanh.approx.f32 %0, %1;" : "=f"(r) : "f"(v)); return r;
}
__device__ __forceinline__ float sigf(float v) { return fmaf(0.5f, tanha(0.5f * v), 0.5f); }
__device__ __forceinline__ float rna_tf32(float v) {
    float r; asm("cvt.rna.tf32.f32 %0, %1;" : "=f"(r) : "f"(v)); return r;
}
__device__ __forceinline__ void mma8(float* d, u32 a0, u32 a1, u32 a2, u32 a3,
                                     u32 b0, u32 b1) {
    asm volatile("mma.sync.aligned.m16n8k8.row.col.f32.tf32.tf32.f32 "
        "{%0,%1,%2,%3}, {%4,%5,%6,%7}, {%8,%9}, {%0,%1,%2,%3};"
        : "+f"(d[0]), "+f"(d[1]), "+f"(d[2]), "+f"(d[3])
        : "r"(a0), "r"(a1), "r"(a2), "r"(a3), "r"(b0), "r"(b1));
}
__device__ __forceinline__ void barpair(int tile) {
    asm volatile("bar.sync %0, %1;" :: "r"(tile + 1), "r"(64) : "memory");
}

// ---- K1: zero cursors + fold weights ----
__global__ void k_init(const float* Wz, const float* bz, const float* Lz, const float* Lzb,
                       const float* Wr, const float* br, const float* Lr, const float* Lrb,
                       const float* Wh, const float* bh, const float* Lh, const float* Lhb,
                       const float* att) {
    int i = blockIdx.x * blockDim.x + threadIdx.x;
    if (i < N_NODES) g_cursor[i] = 0;
    if (blockIdx.x == 0) {
        const float* W[3] = {Wz, Wr, Wh};
        const float* L[3] = {Lz, Lr, Lh};
        const float* B[3] = {bz, br, bh};
        const float* LB[3] = {Lzb, Lrb, Lhb};
        int tid = threadIdx.x;
        for (int idx = tid; idx < 3 * FEAT * OUT; idx += blockDim.x) {
            int g = idx / (FEAT * OUT), r = idx - g * (FEAT * OUT), f = r / OUT, o = r % OUT;
            float s = 0.0f;
            for (int k = 0; k < OUT; k++) s = fmaf(W[g][f * OUT + k], L[g][k * OUT + o], s);
            g_WP[idx] = s;
        }
        for (int idx = tid; idx < 3 * OUT; idx += blockDim.x) {
            int g = idx / OUT, o = idx % OUT;
            float s = LB[g][o];
            for (int k = 0; k < OUT; k++) s = fmaf(B[g][k], L[g][k * OUT + o], s);
            g_BP[idx] = s;
        }
        if (tid == 0) {
            float m = att[0];
            for (int t = 1; t < PERIODS; t++) m = fmaxf(m, att[t]);
            float e[PERIODS], sum = 0.0f;
            for (int t = 0; t < PERIODS; t++) { e[t] = __expf(att[t] - m); sum += e[t]; }
            float inv = __fdividef(1.0f, sum);
            for (int t = 0; t < PERIODS; t++) g_probs[t] = e[t] * inv;
        }
    }
}
__global__ void k_fill(const int* __restrict__ ei) {
    int e = blockIdx.x * blockDim.x + threadIdx.x;
    if (e >= N_EDGES) return;
    int s = ei[e], d = ei[N_EDGES + e];
    int pos = atomicAdd(&g_cursor[d], 1);
    if (pos < CAP) g_srcs[d * CAP + pos] = s;
}

// ---- gather: one warp per node, float4 loads (lanes 0..23), transposed write ----
__global__ void __launch_bounds__(256) k_gather(const float* __restrict__ x) {
    int gw = (blockIdx.x * 256 + threadIdx.x) >> 5;
    if (gw >= N_NODES) return;
    int lane = threadIdx.x & 31, node = gw;
    int deg = g_cursor[node], ndeg = min(deg, CAP);
    const int* bucket = g_srcs + node * CAP;
    const float4* x4 = reinterpret_cast<const float4*>(x);
    float4 acc = make_float4(0.f, 0.f, 0.f, 0.f);
    const bool act = (lane < 24);
    for (int j0 = 0; j0 < ndeg; j0 += 32) {
        int idx = j0 + lane;
        int sj = (idx < ndeg) ? bucket[idx] : 0;
        float dv = (idx < ndeg) ? rsqrtf((float)g_cursor[sj] + 1.0f) : 0.0f;
        int lim = min(32, ndeg - j0);
#pragma unroll 4
        for (int jj = 0; jj < lim; jj++) {
            int s = __shfl_sync(0xffffffffu, sj, jj);
            float d = __shfl_sync(0xffffffffu, dv, jj);
            if (act) {
                float4 v = x4[s * 24 + lane];
                acc.x = fmaf(d, v.x, acc.x);
                acc.y = fmaf(d, v.y, acc.y);
                acc.z = fmaf(d, v.z, acc.z);
                acc.w = fmaf(d, v.w, acc.w);
            }
        }
    }
    if (act) {
        float dd = rsqrtf((float)deg + 1.0f);
        float4 self = x4[node * 24 + lane];
        float* dst = g_Ax + node * XDIM;
        float r[4] = {dd * fmaf(dd, self.x, acc.x), dd * fmaf(dd, self.y, acc.y),
                      dd * fmaf(dd, self.z, acc.z), dd * fmaf(dd, self.w, acc.w)};
#pragma unroll
        for (int q = 0; q < 4; q++) {
            int c = lane * 4 + q;                        // f-major col: f*12 + t
            dst[(c % PERIODS) * 8 + c / PERIODS] = r[q]; // -> t-major t*8 + f
        }
    }
}

// ---- fused mma.sync kernel: 2 warps per 16-row tile (n split 32/32) ----
struct FS2 {
    float  X[MB2][XS];
    float4 WZR[9][8][32];
    float2 WH[9][8][32];
    float  BP[3][OUT];
    float  probs[PERIODS];
};

__device__ __forceinline__ float welem(const float* Lg, int g, int n, int k) {
    return (k < 64) ? Lg[(64 + k) * 64 + n] : g_WP[g * 512 + (k - 64) * 64 + n];
}

__global__ void __launch_bounds__(THR, 1)
k_fused(const float* __restrict__ Lz, const float* __restrict__ Lr,
        const float* __restrict__ Lh, const float* __restrict__ hw,
        const float* __restrict__ hb, float* __restrict__ out) {
    extern __shared__ char smraw[];
    FS2* sm = (FS2*)smraw;
    const int tid = threadIdx.x;
    const int w = tid >> 5, lane = tid & 31;
    const int tile = w >> 1, side = w & 1;
    const int grp = lane >> 2, tig = lane & 3;
    const int wrow = tile * 16;
    const int ntb = side * 4;
    const int nb = blockIdx.x * MB2;

    for (int i = tid; i < 9 * 8 * 32; i += THR) {
        int kb = i / 256, rem = i & 255, nt = rem >> 5, ln = rem & 31;
        int g2 = ln >> 2, t2 = ln & 3;
        int kA = kb * 8 + 2 * t2, kB = kA + 1, nrow = nt * 8 + g2;
        float4 zr;
        zr.x = rna_tf32(welem(Lz, 0, nrow, kA));
        zr.y = rna_tf32(welem(Lz, 0, nrow, kB));
        zr.z = rna_tf32(welem(Lr, 1, nrow, kA));
        zr.w = rna_tf32(welem(Lr, 1, nrow, kB));
        sm->WZR[kb][nt][ln] = zr;
        sm->WH[kb][nt][ln] = make_float2(rna_tf32(welem(Lh, 2, nrow, kA)),
                                         rna_tf32(welem(Lh, 2, nrow, kB)));
    }
    for (int i = tid; i < 3 * OUT; i += THR) (&sm->BP[0][0])[i] = g_BP[i];
    if (tid < PERIODS) sm->probs[tid] = g_probs[tid];
    for (int i = tid; i < MB2 * OUT; i += THR) sm->X[i >> 6][i & 63] = 0.0f;
    __syncthreads();

    const int row0 = wrow + grp, row1 = row0 + 8;
    const int arow = wrow + (lane >> 1);
    const int anode = nb + arow;
    const bool aok = (anode < N_NODES);

    float hacc[16];
#pragma unroll
    for (int i = 0; i < 16; i++) hacc[i] = 0.0f;

    for (int t = 0; t < PERIODS; t++) {
        float p = sm->probs[t];

        if (side == 0) {
            int acol = (lane & 1) * 4;
            float4 av = make_float4(0.f, 0.f, 0.f, 0.f);
            if (aok) av = *(const float4*)(g_Ax + anode * XDIM + t * 8 + acol);
            *(float4*)&sm->X[arow][64 + acol] =
                make_float4(rna_tf32(av.x), rna_tf32(av.y), rna_tf32(av.z), rna_tf32(av.w));
        }
        barpair(tile);

        float2 ax_a = *(float2*)&sm->X[row0][64 + 2 * tig];
        float2 ax_b = *(float2*)&sm->X[row1][64 + 2 * tig];
        u32 x8a0 = __float_as_uint(ax_a.x), x8a2 = __float_as_uint(ax_a.y);
        u32 x8a1 = __float_as_uint(ax_b.x), x8a3 = __float_as_uint(ax_b.y);

        // ---- z and r GEMMs ----
        float az[16], ar[16];
#pragma unroll
        for (int i = 0; i < 16; i++) { az[i] = 0.0f; ar[i] = 0.0f; }
#pragma unroll
        for (int kb = 0; kb < 8; kb++) {
            float2 va = *(float2*)&sm->X[row0][kb * 8 + 2 * tig];
            float2 vb = *(float2*)&sm->X[row1][kb * 8 + 2 * tig];
            u32 a0 = __float_as_uint(va.x), a2 = __float_as_uint(va.y);
            u32 a1 = __float_as_uint(vb.x), a3 = __float_as_uint(vb.y);
#pragma unroll
            for (int nt = 0; nt < 4; nt++) {
                float4 b = sm->WZR[kb][ntb + nt][lane];
                mma8(az + nt * 4, a0, a1, a2, a3, __float_as_uint(b.x), __float_as_uint(b.y));
                mma8(ar + nt * 4, a0, a1, a2, a3, __float_as_uint(b.z), __float_as_uint(b.w));
            }
        }
#pragma unroll
        for (int nt = 0; nt < 4; nt++) {
            float4 b = sm->WZR[8][ntb + nt][lane];
            mma8(az + nt * 4, x8a0, x8a1, x8a2, x8a3, __float_as_uint(b.x), __float_as_uint(b.y));
            mma8(ar + nt * 4, x8a0, x8a1, x8a2, x8a3, __float_as_uint(b.z), __float_as_uint(b.w));
        }

        // ---- epilogue 1 ----
#pragma unroll
        for (int nt = 0; nt < 4; nt++) {
            int c0 = (ntb + nt) * 8 + tig * 2;
            float2 bz = *(float2*)&sm->BP[0][c0];
            float2 br = *(float2*)&sm->BP[1][c0];
            float2 h01 = *(float2*)&sm->X[row0][c0];
            float2 h23 = *(float2*)&sm->X[row1][c0];
            float z0 = sigf(az[nt*4+0] + bz.x), z1 = sigf(az[nt*4+1] + bz.y);
            float z2 = sigf(az[nt*4+2] + bz.x), z3 = sigf(az[nt*4+3] + bz.y);
            float r0 = sigf(ar[nt*4+0] + br.x), r1 = sigf(ar[nt*4+1] + br.y);
            float r2 = sigf(ar[nt*4+2] + br.x), r3 = sigf(ar[nt*4+3] + br.y);
            *(float2*)&sm->X[row0][c0] = make_float2(rna_tf32(r0 * h01.x), rna_tf32(r1 * h01.y));
            *(float2*)&sm->X[row1][c0] = make_float2(rna_tf32(r2 * h23.x), rna_tf32(r3 * h23.y));
            az[nt*4+0] = z0; az[nt*4+1] = z1; az[nt*4+2] = z2; az[nt*4+3] = z3;
            ar[nt*4+0] = h01.x; ar[nt*4+1] = h01.y; ar[nt*4+2] = h23.x; ar[nt*4+3] = h23.y;
        }
        barpair(tile);

        // ---- h GEMM ----
        float ah[16];
#pragma unroll
        for (int i = 0; i < 16; i++) ah[i] = 0.0f;
#pragma unroll
        for (int kb = 0; kb < 8; kb++) {
            float2 va = *(float2*)&sm->X[row0][kb * 8 + 2 * tig];
            float2 vb = *(float2*)&sm->X[row1][kb * 8 + 2 * tig];
            u32 a0 = __float_as_uint(va.x), a2 = __float_as_uint(va.y);
            u32 a1 = __float_as_uint(vb.x), a3 = __float_as_uint(vb.y);
#pragma unroll
            for (int nt = 0; nt < 4; nt++) {
                float2 b = sm->WH[kb][ntb + nt][lane];
                mma8(ah + nt * 4, a0, a1, a2, a3, __float_as_uint(b.x), __float_as_uint(b.y));
            }
        }
#pragma unroll
        for (int nt = 0; nt < 4; nt++) {
            float2 b = sm->WH[8][ntb + nt][lane];
            mma8(ah + nt * 4, x8a0, x8a1, x8a2, x8a3, __float_as_uint(b.x), __float_as_uint(b.y));
        }

        // ---- epilogue 2 ----
#pragma unroll
        for (int nt = 0; nt < 4; nt++) {
            int c0 = (ntb + nt) * 8 + tig * 2;
            float2 bh = *(float2*)&sm->BP[2][c0];
            float hn[4];
#pragma unroll
            for (int q = 0; q < 4; q++) {
                float bb = (q & 1) ? bh.y : bh.x;
                float ht = tanha(ah[nt*4+q] + bb);
                float z = az[nt*4+q], hd = ar[nt*4+q];
                float v = z * hd + (1.0f - z) * ht;
                hacc[nt*4+q] = fmaf(p, v, hacc[nt*4+q]);
                hn[q] = rna_tf32(v);
            }
            *(float2*)&sm->X[row0][c0] = make_float2(hn[0], hn[1]);
            *(float2*)&sm->X[row1][c0] = make_float2(hn[2], hn[3]);
        }
        barpair(tile);
    }

    // ---- head ----
#pragma unroll
    for (int nt = 0; nt < 4; nt++) {
        int c0 = (ntb + nt) * 8 + tig * 2;
        *(float2*)&sm->X[row0][c0] =
            make_float2(fmaxf(hacc[nt*4+0], 0.f), fmaxf(hacc[nt*4+1], 0.f));
        *(float2*)&sm->X[row1][c0] =
            make_float2(fmaxf(hacc[nt*4+2], 0.f), fmaxf(hacc[nt*4+3], 0.f));
    }
    __syncthreads();

    float* sW = (float*)&sm->WZR[0][0][0];
    float* sB = &sm->BP[0][0];
    for (int i = tid; i < OUT * PERIODS; i += THR) sW[i] = hw[i];
    if (tid < PERIODS) sB[tid] = hb[tid];
    __syncthreads();

    for (int i = tid; i < MB2 * PERIODS; i += THR) {
        int nn = i / PERIODS, pp = i - nn * PERIODS;
        int node = nb + nn;
        if (node >= N_NODES) continue;
        float acc = sB[pp];
#pragma unroll 16
        for (int o = 0; o < OUT; o++)
            acc = fmaf(sm->X[nn][o], sW[o * PERIODS + pp], acc);
        out[node * PERIODS + pp] = acc;
    }
}

extern "C" void kernel_launch(void* const* d_in, const int* in_sizes, int n_in,
                              void* d_out, int out_size) {
    const float* x   = (const float*)d_in[0];
    const int*   ei  = (const int*)d_in[1];
    const float* Wz  = (const float*)d_in[2];
    const float* bz  = (const float*)d_in[3];
    const float* LzW = (const float*)d_in[4];
    const float* Lzb = (const float*)d_in[5];
    const float* Wr  = (const float*)d_in[6];
    const float* br  = (const float*)d_in[7];
    const float* LrW = (const float*)d_in[8];
    const float* Lrb = (const float*)d_in[9];
    const float* Wh  = (const float*)d_in[10];
    const float* bh  = (const float*)d_in[11];
    const float* LhW = (const float*)d_in[12];
    const float* Lhb = (const float*)d_in[13];
    const float* att = (const float*)d_in[14];
    const float* hW  = (const float*)d_in[15];
    const float* hb  = (const float*)d_in[16];
    float* out = (float*)d_out;

    cudaFuncSetAttribute(k_fused, cudaFuncAttributeMaxDynamicSharedMemorySize, (int)sizeof(FS2));

    k_init<<<(N_NODES + 255) / 256, 256>>>(Wz, bz, LzW, Lzb, Wr, br, LrW, Lrb,
                                           Wh, bh, LhW, Lhb, att);
    k_fill<<<(N_EDGES + 255) / 256, 256>>>(ei);
    k_gather<<<(N_NODES * 32 + 255) / 256, 256>>>(x);
    k_fused<<<(N_NODES + MB2 - 1) / MB2, THR, sizeof(FS2)>>>(LzW, LrW, LhW, hW, hb, out);
}

// round 17
// speedup vs baseline: 1.0684x; 1.0156x over previous
#include <cuda_runtime.h>
#include <cstdint>

#define N_NODES 20000
#define N_EDGES 640000
#define FEAT 8
#define OUT 64
#define PERIODS 12
#define XDIM 96
#define CAP 128
#define MB2 144
#define THR 576
#define XS 84   // X smem row stride (floats)

typedef unsigned long long u64;
typedef unsigned int u32;

__device__ __align__(16) int   g_cursor[N_NODES];
__device__ __align__(16) int   g_srcs[N_NODES * CAP];
__device__ __align__(16) float g_Ax[N_NODES * XDIM];   // t-major rows
__device__ __align__(16) float g_WP[3 * FEAT * OUT];
__device__ __align__(16) float g_BP[3 * OUT];
__device__ float g_probs[PERIODS];

__device__ __forceinline__ float tanha(float v) {
    float r; asm("tanh.approx.f32 %0, %1;" : "=f"(r) : "f"(v)); return r;
}
__device__ __forceinline__ float sigf(float v) { return fmaf(0.5f, tanha(0.5f * v), 0.5f); }
__device__ __forceinline__ float rna_tf32(float v) {
    float r; asm("cvt.rna.tf32.f32 %0, %1;" : "=f"(r) : "f"(v)); return r;
}
__device__ __forceinline__ void mma8(float* d, u32 a0, u32 a1, u32 a2, u32 a3,
                                     u32 b0, u32 b1) {
    asm volatile("mma.sync.aligned.m16n8k8.row.col.f32.tf32.tf32.f32 "
        "{%0,%1,%2,%3}, {%4,%5,%6,%7}, {%8,%9}, {%0,%1,%2,%3};"
        : "+f"(d[0]), "+f"(d[1]), "+f"(d[2]), "+f"(d[3])
        : "r"(a0), "r"(a1), "r"(a2), "r"(a3), "r"(b0), "r"(b1));
}
__device__ __forceinline__ void barpair(int tile) {
    asm volatile("bar.sync %0, %1;" :: "r"(tile + 1), "r"(64) : "memory");
}

// ---- K1: zero cursors + fold weights ----
__global__ void k_init(const float* Wz, const float* bz, const float* Lz, const float* Lzb,
                       const float* Wr, const float* br, const float* Lr, const float* Lrb,
                       const float* Wh, const float* bh, const float* Lh, const float* Lhb,
                       const float* att) {
    int i = blockIdx.x * blockDim.x + threadIdx.x;
    if (i < N_NODES) g_cursor[i] = 0;
    if (blockIdx.x == 0) {
        const float* W[3] = {Wz, Wr, Wh};
        const float* L[3] = {Lz, Lr, Lh};
        const float* B[3] = {bz, br, bh};
        const float* LB[3] = {Lzb, Lrb, Lhb};
        int tid = threadIdx.x;
        for (int idx = tid; idx < 3 * FEAT * OUT; idx += blockDim.x) {
            int g = idx / (FEAT * OUT), r = idx - g * (FEAT * OUT), f = r / OUT, o = r % OUT;
            float s = 0.0f;
            for (int k = 0; k < OUT; k++) s = fmaf(W[g][f * OUT + k], L[g][k * OUT + o], s);
            g_WP[idx] = s;
        }
        for (int idx = tid; idx < 3 * OUT; idx += blockDim.x) {
            int g = idx / OUT, o = idx % OUT;
            float s = LB[g][o];
            for (int k = 0; k < OUT; k++) s = fmaf(B[g][k], L[g][k * OUT + o], s);
            g_BP[idx] = s;
        }
        if (tid == 0) {
            float m = att[0];
            for (int t = 1; t < PERIODS; t++) m = fmaxf(m, att[t]);
            float e[PERIODS], sum = 0.0f;
            for (int t = 0; t < PERIODS; t++) { e[t] = __expf(att[t] - m); sum += e[t]; }
            float inv = __fdividef(1.0f, sum);
            for (int t = 0; t < PERIODS; t++) g_probs[t] = e[t] * inv;
        }
    }
}
__global__ void k_fill(const int* __restrict__ ei) {
    int e = blockIdx.x * blockDim.x + threadIdx.x;
    if (e >= N_EDGES) return;
    int s = ei[e], d = ei[N_EDGES + e];
    int pos = atomicAdd(&g_cursor[d], 1);
    if (pos < CAP) g_srcs[d * CAP + pos] = s;
}

// ---- gather: one warp per node, float4 loads (lanes 0..23), transposed write ----
__global__ void __launch_bounds__(256) k_gather(const float* __restrict__ x) {
    int gw = (blockIdx.x * 256 + threadIdx.x) >> 5;
    if (gw >= N_NODES) return;
    int lane = threadIdx.x & 31, node = gw;
    int deg = g_cursor[node], ndeg = min(deg, CAP);
    const int* bucket = g_srcs + node * CAP;
    const float4* x4 = reinterpret_cast<const float4*>(x);
    float4 acc = make_float4(0.f, 0.f, 0.f, 0.f);
    const bool act = (lane < 24);
    for (int j0 = 0; j0 < ndeg; j0 += 32) {
        int idx = j0 + lane;
        int sj = (idx < ndeg) ? bucket[idx] : 0;
        float dv = (idx < ndeg) ? rsqrtf((float)g_cursor[sj] + 1.0f) : 0.0f;
        int lim = min(32, ndeg - j0);
#pragma unroll 4
        for (int jj = 0; jj < lim; jj++) {
            int s = __shfl_sync(0xffffffffu, sj, jj);
            float d = __shfl_sync(0xffffffffu, dv, jj);
            if (act) {
                float4 v = x4[s * 24 + lane];
                acc.x = fmaf(d, v.x, acc.x);
                acc.y = fmaf(d, v.y, acc.y);
                acc.z = fmaf(d, v.z, acc.z);
                acc.w = fmaf(d, v.w, acc.w);
            }
        }
    }
    if (act) {
        float dd = rsqrtf((float)deg + 1.0f);
        float4 self = x4[node * 24 + lane];
        float* dst = g_Ax + node * XDIM;
        float r[4] = {dd * fmaf(dd, self.x, acc.x), dd * fmaf(dd, self.y, acc.y),
                      dd * fmaf(dd, self.z, acc.z), dd * fmaf(dd, self.w, acc.w)};
#pragma unroll
        for (int q = 0; q < 4; q++) {
            int c = lane * 4 + q;                        // f-major col: f*12 + t
            dst[(c % PERIODS) * 8 + c / PERIODS] = r[q]; // -> t-major t*8 + f
        }
    }
}

// ---- fused mma.sync kernel: 2 warps per 16-row tile (n split 32/32) ----
struct FS2 {
    float  X[MB2][XS];
    float4 WZR[9][8][32];
    float2 WH[9][8][32];
    float  BP[3][OUT];
    float  probs[PERIODS];
};

__device__ __forceinline__ float welem(const float* Lg, int g, int n, int k) {
    return (k < 64) ? Lg[(64 + k) * 64 + n] : g_WP[g * 512 + (k - 64) * 64 + n];
}

__global__ void __launch_bounds__(THR, 1)
k_fused(const float* __restrict__ Lz, const float* __restrict__ Lr,
        const float* __restrict__ Lh, const float* __restrict__ hw,
        const float* __restrict__ hb, float* __restrict__ out) {
    extern __shared__ char smraw[];
    FS2* sm = (FS2*)smraw;
    const int tid = threadIdx.x;
    const int w = tid >> 5, lane = tid & 31;
    const int tile = w >> 1, side = w & 1;
    const int grp = lane >> 2, tig = lane & 3;
    const int wrow = tile * 16;
    const int ntb = side * 4;
    const int nb = blockIdx.x * MB2;

    for (int i = tid; i < 9 * 8 * 32; i += THR) {
        int kb = i / 256, rem = i & 255, nt = rem >> 5, ln = rem & 31;
        int g2 = ln >> 2, t2 = ln & 3;
        int kA = kb * 8 + 2 * t2, kB = kA + 1, nrow = nt * 8 + g2;
        float4 zr;
        zr.x = rna_tf32(welem(Lz, 0, nrow, kA));
        zr.y = rna_tf32(welem(Lz, 0, nrow, kB));
        zr.z = rna_tf32(welem(Lr, 1, nrow, kA));
        zr.w = rna_tf32(welem(Lr, 1, nrow, kB));
        sm->WZR[kb][nt][ln] = zr;
        sm->WH[kb][nt][ln] = make_float2(rna_tf32(welem(Lh, 2, nrow, kA)),
                                         rna_tf32(welem(Lh, 2, nrow, kB)));
    }
    for (int i = tid; i < 3 * OUT; i += THR) (&sm->BP[0][0])[i] = g_BP[i];
    if (tid < PERIODS) sm->probs[tid] = g_probs[tid];
    // NOTE: no X zero-init — t=0 peel never reads H cols, epi2 writes all of them
    __syncthreads();

    const int row0 = wrow + grp, row1 = row0 + 8;
    const int arow = wrow + (lane >> 1);
    const int anode = nb + arow;
    const bool aok = (anode < N_NODES);

    float hacc[16];
#pragma unroll
    for (int i = 0; i < 16; i++) hacc[i] = 0.0f;

    // ================= t = 0 (peeled: H == 0 exactly) =================
    {
        float p = sm->probs[0];
        if (side == 0) {
            int acol = (lane & 1) * 4;
            float4 av = make_float4(0.f, 0.f, 0.f, 0.f);
            if (aok) av = *(const float4*)(g_Ax + anode * XDIM + 0 + acol);
            *(float4*)&sm->X[arow][64 + acol] =
                make_float4(rna_tf32(av.x), rna_tf32(av.y), rna_tf32(av.z), rna_tf32(av.w));
        }
        barpair(tile);

        float2 ax_a = *(float2*)&sm->X[row0][64 + 2 * tig];
        float2 ax_b = *(float2*)&sm->X[row1][64 + 2 * tig];
        u32 x8a0 = __float_as_uint(ax_a.x), x8a2 = __float_as_uint(ax_a.y);
        u32 x8a1 = __float_as_uint(ax_b.x), x8a3 = __float_as_uint(ax_b.y);

        float az[16], ah[16];
#pragma unroll
        for (int i = 0; i < 16; i++) { az[i] = 0.0f; ah[i] = 0.0f; }
#pragma unroll
        for (int nt = 0; nt < 4; nt++) {
            float4 b = sm->WZR[8][ntb + nt][lane];
            mma8(az + nt * 4, x8a0, x8a1, x8a2, x8a3, __float_as_uint(b.x), __float_as_uint(b.y));
            float2 bh = sm->WH[8][ntb + nt][lane];
            mma8(ah + nt * 4, x8a0, x8a1, x8a2, x8a3, __float_as_uint(bh.x), __float_as_uint(bh.y));
        }
        // epi (H=0): hn = (1-z)*tanh(ah+bh)
#pragma unroll
        for (int nt = 0; nt < 4; nt++) {
            int c0 = (ntb + nt) * 8 + tig * 2;
            float2 bz = *(float2*)&sm->BP[0][c0];
            float2 bh = *(float2*)&sm->BP[2][c0];
            float hn[4];
#pragma unroll
            for (int q = 0; q < 4; q++) {
                float zb = (q & 1) ? bz.y : bz.x;
                float bb = (q & 1) ? bh.y : bh.x;
                float z = sigf(az[nt*4+q] + zb);
                float ht = tanha(ah[nt*4+q] + bb);
                float v = (1.0f - z) * ht;
                hacc[nt*4+q] = fmaf(p, v, hacc[nt*4+q]);
                hn[q] = rna_tf32(v);
            }
            *(float2*)&sm->X[row0][c0] = make_float2(hn[0], hn[1]);
            *(float2*)&sm->X[row1][c0] = make_float2(hn[2], hn[3]);
        }
        barpair(tile);
    }

    // ================= t = 1 .. 11 =================
    for (int t = 1; t < PERIODS; t++) {
        float p = sm->probs[t];
        const bool last = (t == PERIODS - 1);

        if (side == 0) {
            int acol = (lane & 1) * 4;
            float4 av = make_float4(0.f, 0.f, 0.f, 0.f);
            if (aok) av = *(const float4*)(g_Ax + anode * XDIM + t * 8 + acol);
            *(float4*)&sm->X[arow][64 + acol] =
                make_float4(rna_tf32(av.x), rna_tf32(av.y), rna_tf32(av.z), rna_tf32(av.w));
        }
        barpair(tile);

        float2 ax_a = *(float2*)&sm->X[row0][64 + 2 * tig];
        float2 ax_b = *(float2*)&sm->X[row1][64 + 2 * tig];
        u32 x8a0 = __float_as_uint(ax_a.x), x8a2 = __float_as_uint(ax_a.y);
        u32 x8a1 = __float_as_uint(ax_b.x), x8a3 = __float_as_uint(ax_b.y);

        // ---- z and r GEMMs ----
        float az[16], ar[16];
#pragma unroll
        for (int i = 0; i < 16; i++) { az[i] = 0.0f; ar[i] = 0.0f; }
#pragma unroll
        for (int kb = 0; kb < 8; kb++) {
            float2 va = *(float2*)&sm->X[row0][kb * 8 + 2 * tig];
            float2 vb = *(float2*)&sm->X[row1][kb * 8 + 2 * tig];
            u32 a0 = __float_as_uint(va.x), a2 = __float_as_uint(va.y);
            u32 a1 = __float_as_uint(vb.x), a3 = __float_as_uint(vb.y);
#pragma unroll
            for (int nt = 0; nt < 4; nt++) {
                float4 b = sm->WZR[kb][ntb + nt][lane];
                mma8(az + nt * 4, a0, a1, a2, a3, __float_as_uint(b.x), __float_as_uint(b.y));
                mma8(ar + nt * 4, a0, a1, a2, a3, __float_as_uint(b.z), __float_as_uint(b.w));
            }
        }
#pragma unroll
        for (int nt = 0; nt < 4; nt++) {
            float4 b = sm->WZR[8][ntb + nt][lane];
            mma8(az + nt * 4, x8a0, x8a1, x8a2, x8a3, __float_as_uint(b.x), __float_as_uint(b.y));
            mma8(ar + nt * 4, x8a0, x8a1, x8a2, x8a3, __float_as_uint(b.z), __float_as_uint(b.w));
        }

        // ---- epilogue 1 ----
#pragma unroll
        for (int nt = 0; nt < 4; nt++) {
            int c0 = (ntb + nt) * 8 + tig * 2;
            float2 bz = *(float2*)&sm->BP[0][c0];
            float2 br = *(float2*)&sm->BP[1][c0];
            float2 h01 = *(float2*)&sm->X[row0][c0];
            float2 h23 = *(float2*)&sm->X[row1][c0];
            float z0 = sigf(az[nt*4+0] + bz.x), z1 = sigf(az[nt*4+1] + bz.y);
            float z2 = sigf(az[nt*4+2] + bz.x), z3 = sigf(az[nt*4+3] + bz.y);
            float r0 = sigf(ar[nt*4+0] + br.x), r1 = sigf(ar[nt*4+1] + br.y);
            float r2 = sigf(ar[nt*4+2] + br.x), r3 = sigf(ar[nt*4+3] + br.y);
            *(float2*)&sm->X[row0][c0] = make_float2(rna_tf32(r0 * h01.x), rna_tf32(r1 * h01.y));
            *(float2*)&sm->X[row1][c0] = make_float2(rna_tf32(r2 * h23.x), rna_tf32(r3 * h23.y));
            az[nt*4+0] = z0; az[nt*4+1] = z1; az[nt*4+2] = z2; az[nt*4+3] = z3;
            ar[nt*4+0] = h01.x; ar[nt*4+1] = h01.y; ar[nt*4+2] = h23.x; ar[nt*4+3] = h23.y;
        }
        barpair(tile);

        // ---- h GEMM ----
        float ah[16];
#pragma unroll
        for (int i = 0; i < 16; i++) ah[i] = 0.0f;
#pragma unroll
        for (int kb = 0; kb < 8; kb++) {
            float2 va = *(float2*)&sm->X[row0][kb * 8 + 2 * tig];
            float2 vb = *(float2*)&sm->X[row1][kb * 8 + 2 * tig];
            u32 a0 = __float_as_uint(va.x), a2 = __float_as_uint(va.y);
            u32 a1 = __float_as_uint(vb.x), a3 = __float_as_uint(vb.y);
#pragma unroll
            for (int nt = 0; nt < 4; nt++) {
                float2 b = sm->WH[kb][ntb + nt][lane];
                mma8(ah + nt * 4, a0, a1, a2, a3, __float_as_uint(b.x), __float_as_uint(b.y));
            }
        }
#pragma unroll
        for (int nt = 0; nt < 4; nt++) {
            float2 b = sm->WH[8][ntb + nt][lane];
            mma8(ah + nt * 4, x8a0, x8a1, x8a2, x8a3, __float_as_uint(b.x), __float_as_uint(b.y));
        }

        // ---- epilogue 2 (stores dead at t=11) ----
#pragma unroll
        for (int nt = 0; nt < 4; nt++) {
            int c0 = (ntb + nt) * 8 + tig * 2;
            float2 bh = *(float2*)&sm->BP[2][c0];
            float hn[4];
#pragma unroll
            for (int q = 0; q < 4; q++) {
                float bb = (q & 1) ? bh.y : bh.x;
                float ht = tanha(ah[nt*4+q] + bb);
                float z = az[nt*4+q], hd = ar[nt*4+q];
                float v = z * hd + (1.0f - z) * ht;
                hacc[nt*4+q] = fmaf(p, v, hacc[nt*4+q]);
                hn[q] = rna_tf32(v);
            }
            if (!last) {
                *(float2*)&sm->X[row0][c0] = make_float2(hn[0], hn[1]);
                *(float2*)&sm->X[row1][c0] = make_float2(hn[2], hn[3]);
            }
        }
        barpair(tile);   // needed even at t=11: partner's h GEMM reads X before head overwrites
    }

    // ---- head ----
#pragma unroll
    for (int nt = 0; nt < 4; nt++) {
        int c0 = (ntb + nt) * 8 + tig * 2;
        *(float2*)&sm->X[row0][c0] =
            make_float2(fmaxf(hacc[nt*4+0], 0.f), fmaxf(hacc[nt*4+1], 0.f));
        *(float2*)&sm->X[row1][c0] =
            make_float2(fmaxf(hacc[nt*4+2], 0.f), fmaxf(hacc[nt*4+3], 0.f));
    }
    __syncthreads();

    float* sW = (float*)&sm->WZR[0][0][0];
    float* sB = &sm->BP[0][0];
    for (int i = tid; i < OUT * PERIODS; i += THR) sW[i] = hw[i];
    if (tid < PERIODS) sB[tid] = hb[tid];
    __syncthreads();

    for (int i = tid; i < MB2 * PERIODS; i += THR) {
        int nn = i / PERIODS, pp = i - nn * PERIODS;
        int node = nb + nn;
        if (node >= N_NODES) continue;
        float acc = sB[pp];
#pragma unroll 16
        for (int o = 0; o < OUT; o++)
            acc = fmaf(sm->X[nn][o], sW[o * PERIODS + pp], acc);
        out[node * PERIODS + pp] = acc;
    }
}

extern "C" void kernel_launch(void* const* d_in, const int* in_sizes, int n_in,
                              void* d_out, int out_size) {
    const float* x   = (const float*)d_in[0];
    const int*   ei  = (const int*)d_in[1];
    const float* Wz  = (const float*)d_in[2];
    const float* bz  = (const float*)d_in[3];
    const float* LzW = (const float*)d_in[4];
    const float* Lzb = (const float*)d_in[5];
    const float* Wr  = (const float*)d_in[6];
    const float* br  = (const float*)d_in[7];
    const float* LrW = (const float*)d_in[8];
    const float* Lrb = (const float*)d_in[9];
    const float* Wh  = (const float*)d_in[10];
    const float* bh  = (const float*)d_in[11];
    const float* LhW = (const float*)d_in[12];
    const float* Lhb = (const float*)d_in[13];
    const float* att = (const float*)d_in[14];
    const float* hW  = (const float*)d_in[15];
    const float* hb  = (const float*)d_in[16];
    float* out = (float*)d_out;

    cudaFuncSetAttribute(k_fused, cudaFuncAttributeMaxDynamicSharedMemorySize, (int)sizeof(FS2));

    k_init<<<(N_NODES + 255) / 256, 256>>>(Wz, bz, LzW, Lzb, Wr, br, LrW, Lrb,
                                           Wh, bh, LhW, Lhb, att);
    k_fill<<<(N_EDGES + 255) / 256, 256>>>(ei);
    k_gather<<<(N_NODES * 32 + 255) / 256, 256>>>(x);
    k_fused<<<(N_NODES + MB2 - 1) / MB2, THR, sizeof(FS2)>>>(LzW, LrW, LhW, hW, hb, out);
}